// round 6
// baseline (speedup 1.0000x reference)
#include <cuda_runtime.h>

// Problem constants (fixed by setup_inputs)
#define DD   2048          // D
#define UU   37            // units
#define BB   16            // batch
#define CHUNK 8192         // floats per chunk of the D*D plane
#define NCHUNK ((DD*DD)/CHUNK)   // 512
#define NTHREADS 256
#define F4_PER_THREAD (CHUNK / 4 / NTHREADS)  // 8 float4 per thread

#define NDIAG  (UU * DD)                      // 75776 diagonal elems
#define GBLOCKS (NDIAG / NTHREADS)            // 296 (exact)
#define SLICES_PER_U (DD / NTHREADS)          // 8
#define NDVALS (BB + 1)                       // 17: [acc1, acc2[0..15]]
#define NBLOCKS (NCHUNK + GBLOCKS)            // 808

// Scratch (device globals; no allocation allowed)
__device__ float g_Spart[UU * NCHUNK];            // dense partials [u][chunk]
__device__ float g_diagpart[GBLOCKS * NDVALS];    // diag partials [slice][17]
__device__ unsigned int g_count = 0;              // arrival counter (self-resets)

// Single fused kernel:
//  blocks [0, NCHUNK):        dense contraction partials — weight read once,
//                             relu(matrix) chunk cached in SHARED MEMORY
//                             (keeps regs low -> 1-wave occupancy).
//  blocks [NCHUNK, NBLOCKS):  diagonal-term partial sums (cheap, overlapped).
//  last block to finish:      finalize all (b, u) outputs from L2 partials.
__global__ void __launch_bounds__(NTHREADS, 6) gfrm_fused_kernel(
    const float* __restrict__ inputs,
    const float* __restrict__ matrix,
    const float* __restrict__ weight,
    const float* __restrict__ bias,
    float* __restrict__ out)
{
    const int tid  = threadIdx.x;
    const int lane = tid & 31;
    const int wid  = tid >> 5;

    __shared__ float4 sm_m[CHUNK / 4];              // 32 KB relu(matrix) cache
    __shared__ float  sm_part[UU][NTHREADS / 32];   // warp partials (dense)

    if (blockIdx.x >= NCHUNK) {
        // ---- diagonal stage: one block per 256-element slice of one u ----
        const int slice = blockIdx.x - NCHUNK;        // 0..295
        const int g = slice * NTHREADS + tid;         // global diag index
        const int u = g >> 11;                        // constant per block
        const int i = g & (DD - 1);

        const float mii = matrix[(size_t)i * (DD + 1)];
        const float wii = __ldcs(weight + (size_t)u * DD * DD
                                        + (size_t)i * (DD + 1));

        float v[NDVALS];
        v[0] = fmaxf(mii, 0.0f) * wii;                // plain-diag term
#pragma unroll
        for (int b = 0; b < BB; b++) {
            const float x = inputs[b * DD + i];
            v[1 + b] = fmaxf(mii * x, 0.0f) * wii;    // batch-diag terms
        }

        // deterministic warp reduce of all 17 values
#pragma unroll
        for (int k = 0; k < NDVALS; k++) {
#pragma unroll
            for (int o = 16; o > 0; o >>= 1)
                v[k] += __shfl_xor_sync(0xffffffffu, v[k], o);
        }
        if (lane == 0) {
#pragma unroll
            for (int k = 0; k < NDVALS; k++) sm_part[k][wid] = v[k];
        }
        __syncthreads();
        if (tid < NDVALS) {
            float s = 0.f;
#pragma unroll
            for (int w = 0; w < NTHREADS / 32; w++) s += sm_part[tid][w];
            g_diagpart[slice * NDVALS + tid] = s;
        }
    } else {
        // ---- dense partial stage ----
        const int c = blockIdx.x;               // chunk id, 0..NCHUNK-1
        const size_t base = (size_t)c * CHUNK;  // float offset into D*D plane

        // Load + relu the matrix chunk into SMEM (coalesced float4).
        const float4* mp = reinterpret_cast<const float4*>(matrix + base);
#pragma unroll
        for (int k = 0; k < F4_PER_THREAD; k++) {
            float4 v = mp[k * NTHREADS + tid];
            v.x = fmaxf(v.x, 0.0f);
            v.y = fmaxf(v.y, 0.0f);
            v.z = fmaxf(v.z, 0.0f);
            v.w = fmaxf(v.w, 0.0f);
            sm_m[k * NTHREADS + tid] = v;
        }
        __syncthreads();

        for (int u = 0; u < UU; u++) {
            const float4* wp = reinterpret_cast<const float4*>(
                weight + (size_t)u * DD * DD + base);
            float s0 = 0.f, s1 = 0.f, s2 = 0.f, s3 = 0.f;
#pragma unroll
            for (int k = 0; k < F4_PER_THREAD; k++) {
                float4 w = __ldcs(wp + k * NTHREADS + tid);  // read-once stream
                float4 m = sm_m[k * NTHREADS + tid];
                s0 = fmaf(m.x, w.x, s0);
                s1 = fmaf(m.y, w.y, s1);
                s2 = fmaf(m.z, w.z, s2);
                s3 = fmaf(m.w, w.w, s3);
            }
            float s = (s0 + s1) + (s2 + s3);
            // deterministic warp reduce
#pragma unroll
            for (int o = 16; o > 0; o >>= 1)
                s += __shfl_xor_sync(0xffffffffu, s, o);
            if (lane == 0) sm_part[u][wid] = s;
        }
        __syncthreads();

        if (tid < UU) {
            float s = 0.f;
#pragma unroll
            for (int w = 0; w < NTHREADS / 32; w++) s += sm_part[tid][w];
            g_Spart[tid * NCHUNK + c] = s;
        }
    }

    // ---- last-block finalize (threadfence-reduction pattern) ----
    __shared__ bool is_last;
    __syncthreads();                 // partial writes done block-wide
    if (tid == 0) {
        __threadfence();             // make partials visible chip-wide
        unsigned int prev = atomicAdd(&g_count, 1u);
        is_last = (prev == NBLOCKS - 1);
    }
    __syncthreads();
    if (!is_last) return;

    if (tid == 0) g_count = 0;       // reset for next graph replay
    __threadfence();                 // acquire side: order reads after arrival

    // Warp-parallel finalize: warp w handles units u = w, w+8, ...
    for (int u = wid; u < UU; u += NTHREADS / 32) {
        // Reduce 512 dense partials (16 per lane, fixed order).
        float s = 0.f;
#pragma unroll
        for (int k = 0; k < NCHUNK / 32; k++)
            s += g_Spart[u * NCHUNK + k * 32 + lane];
#pragma unroll
        for (int o = 16; o > 0; o >>= 1)
            s += __shfl_xor_sync(0xffffffffu, s, o);   // all lanes hold S

        // Reduce 8 diag slice-partials for this u (lanes 0..16).
        float d = 0.f;
        if (lane < NDVALS) {
#pragma unroll
            for (int sl = 0; sl < SLICES_PER_U; sl++)
                d += g_diagpart[(u * SLICES_PER_U + sl) * NDVALS + lane];
        }
        const float d0 = __shfl_sync(0xffffffffu, d, 0);

        if (lane >= 1 && lane <= BB) {
            out[(lane - 1) * UU + u] = s - d0 + d + bias[u];
        }
    }
}

extern "C" void kernel_launch(void* const* d_in, const int* in_sizes, int n_in,
                              void* d_out, int out_size)
{
    const float* inputs = (const float*)d_in[0];  // (16, 2048)
    const float* matrix = (const float*)d_in[1];  // (2048, 2048)
    const float* weight = (const float*)d_in[2];  // (37, 2048, 2048)
    const float* bias   = (const float*)d_in[3];  // (37,)
    float* out = (float*)d_out;                    // (16, 37)

    gfrm_fused_kernel<<<NBLOCKS, NTHREADS>>>(inputs, matrix, weight, bias, out);
}

// round 9
// speedup vs baseline: 1.6338x; 1.6338x over previous
#include <cuda_runtime.h>

// Problem constants (fixed by setup_inputs)
#define DD   2048          // D
#define UU   37            // units
#define BB   16            // batch
#define CHUNK 8192         // floats per chunk of the D*D plane
#define NCHUNK ((DD*DD)/CHUNK)   // 512
#define NTHREADS 256
#define F4_PER_THREAD (CHUNK / 4 / NTHREADS)  // 8 float4 per thread

#define NDIAG  (UU * DD)                      // 75776 diagonal elems
#define GBLOCKS (NDIAG / NTHREADS)            // 296 (exact)
#define SLICES_PER_U (DD / NTHREADS)          // 8
#define NDVALS (BB + 1)                       // 17: [acc1, acc2[0..15]]
#define NWORK  (NCHUNK + GBLOCKS)             // 808 producer blocks
#define NBLOCKS (NWORK + UU)                  // + 37 finalize blocks = 845

// Scratch (device globals; no allocation allowed)
__device__ float g_Spart[UU * NCHUNK];            // dense partials [u][chunk]
__device__ float g_diagpart[GBLOCKS * NDVALS];    // diag partials [slice][17]
__device__ unsigned int g_count = 0;              // producer arrivals
__device__ unsigned int g_fin   = 0;              // finalize arrivals

__global__ void __launch_bounds__(NTHREADS) gfrm_fused_kernel(
    const float* __restrict__ inputs,
    const float* __restrict__ matrix,
    const float* __restrict__ weight,
    const float* __restrict__ bias,
    float* __restrict__ out)
{
    const int tid  = threadIdx.x;
    const int lane = tid & 31;
    const int wid  = tid >> 5;

    // ================= FINALIZE BLOCKS (one per u) =================
    if (blockIdx.x >= NWORK) {
        const int u = blockIdx.x - NWORK;

        if (tid == 0) {
            // Sleep-spin until all producer blocks have published partials.
            while (atomicAdd(&g_count, 0u) != NWORK) __nanosleep(256);
            __threadfence();   // acquire: order partial reads after counter
        }
        __syncthreads();

        // Reduce 512 dense partials for this u (L2 loads, fixed order).
        float s = __ldcg(&g_Spart[u * NCHUNK + tid])
                + __ldcg(&g_Spart[u * NCHUNK + NTHREADS + tid]);
#pragma unroll
        for (int o = 16; o > 0; o >>= 1)
            s += __shfl_xor_sync(0xffffffffu, s, o);

        __shared__ float ws[NTHREADS / 32];
        __shared__ float diag[NDVALS];
        if (lane == 0) ws[wid] = s;

        // Reduce 8 diag slice-partials for this u (lanes 0..16 of warp 0+).
        if (tid < NDVALS) {
            float d = 0.f;
#pragma unroll
            for (int sl = 0; sl < SLICES_PER_U; sl++)
                d += __ldcg(&g_diagpart[(u * SLICES_PER_U + sl) * NDVALS + tid]);
            diag[tid] = d;
        }
        __syncthreads();

        if (tid < BB) {
            float S = 0.f;
#pragma unroll
            for (int w = 0; w < NTHREADS / 32; w++) S += ws[w];
            out[tid * UU + u] = S - diag[0] + diag[1 + tid] + bias[u];
        }

        // Last finalize block resets counters for next graph replay.
        __syncthreads();
        if (tid == 0) {
            __threadfence();
            unsigned int prev = atomicAdd(&g_fin, 1u);
            if (prev == UU - 1) {
                g_count = 0;
                g_fin = 0;
            }
        }
        return;
    }

    // ================= PRODUCER BLOCKS =================
    if (blockIdx.x >= NCHUNK) {
        // ---- diagonal stage: one block per 256-element slice of one u ----
        const int slice = blockIdx.x - NCHUNK;        // 0..295
        const int g = slice * NTHREADS + tid;         // global diag index
        const int u = g >> 11;                        // constant per block
        const int i = g & (DD - 1);

        const float mii = matrix[(size_t)i * (DD + 1)];
        const float wii = __ldcs(weight + (size_t)u * DD * DD
                                        + (size_t)i * (DD + 1));

        float v[NDVALS];
        v[0] = fmaxf(mii, 0.0f) * wii;                // plain-diag term
#pragma unroll
        for (int b = 0; b < BB; b++) {
            const float x = inputs[b * DD + i];
            v[1 + b] = fmaxf(mii * x, 0.0f) * wii;    // batch-diag terms
        }

        // deterministic warp reduce of all 17 values
#pragma unroll
        for (int k = 0; k < NDVALS; k++) {
#pragma unroll
            for (int o = 16; o > 0; o >>= 1)
                v[k] += __shfl_xor_sync(0xffffffffu, v[k], o);
        }
        __shared__ float wp[NDVALS][NTHREADS / 32];
        if (lane == 0) {
#pragma unroll
            for (int k = 0; k < NDVALS; k++) wp[k][wid] = v[k];
        }
        __syncthreads();
        if (tid < NDVALS) {
            float s = 0.f;
#pragma unroll
            for (int w = 0; w < NTHREADS / 32; w++) s += wp[tid][w];
            g_diagpart[slice * NDVALS + tid] = s;
        }
    } else {
        // ---- dense partial stage (register m-cache: MLP needs the regs) ----
        const int c = blockIdx.x;               // chunk id, 0..NCHUNK-1
        const size_t base = (size_t)c * CHUNK;  // float offset into D*D plane

        float4 m[F4_PER_THREAD];
        const float4* mp = reinterpret_cast<const float4*>(matrix + base);
#pragma unroll
        for (int k = 0; k < F4_PER_THREAD; k++) {
            float4 v = mp[k * NTHREADS + tid];
            m[k].x = fmaxf(v.x, 0.0f);
            m[k].y = fmaxf(v.y, 0.0f);
            m[k].z = fmaxf(v.z, 0.0f);
            m[k].w = fmaxf(v.w, 0.0f);
        }

        __shared__ float warp_part[UU][NTHREADS / 32];

        for (int u = 0; u < UU; u++) {
            const float4* wp = reinterpret_cast<const float4*>(
                weight + (size_t)u * DD * DD + base);
            float s0 = 0.f, s1 = 0.f, s2 = 0.f, s3 = 0.f;
#pragma unroll
            for (int k = 0; k < F4_PER_THREAD; k++) {
                float4 w = __ldcs(wp + k * NTHREADS + tid);  // read-once stream
                s0 = fmaf(m[k].x, w.x, s0);
                s1 = fmaf(m[k].y, w.y, s1);
                s2 = fmaf(m[k].z, w.z, s2);
                s3 = fmaf(m[k].w, w.w, s3);
            }
            float s = (s0 + s1) + (s2 + s3);
            // deterministic warp reduce
#pragma unroll
            for (int o = 16; o > 0; o >>= 1)
                s += __shfl_xor_sync(0xffffffffu, s, o);
            if (lane == 0) warp_part[u][wid] = s;
        }
        __syncthreads();

        if (tid < UU) {
            float s = 0.f;
#pragma unroll
            for (int w = 0; w < NTHREADS / 32; w++) s += warp_part[tid][w];
            g_Spart[tid * NCHUNK + c] = s;
        }
    }

    // ---- producer arrival: release partials, bump counter ----
    __syncthreads();
    if (tid == 0) {
        __threadfence();
        atomicAdd(&g_count, 1u);
    }
}

extern "C" void kernel_launch(void* const* d_in, const int* in_sizes, int n_in,
                              void* d_out, int out_size)
{
    const float* inputs = (const float*)d_in[0];  // (16, 2048)
    const float* matrix = (const float*)d_in[1];  // (2048, 2048)
    const float* weight = (const float*)d_in[2];  // (37, 2048, 2048)
    const float* bias   = (const float*)d_in[3];  // (37,)
    float* out = (float*)d_out;                    // (16, 37)

    gfrm_fused_kernel<<<NBLOCKS, NTHREADS>>>(inputs, matrix, weight, bias, out);
}